// round 15
// baseline (speedup 1.0000x reference)
#include <cuda_runtime.h>

#define BATCH 8
#define DIM   384
#define CC    96
#define HIN   128
#define NN    1024
#define NH    4
#define HD    24
#define KVP   28      // padded kv smem row (conflict-free mma B loads)
#define WSP   104     // padded W smem row stride (conflict-free B frags)
#define ITP   36      // padded inT row stride (16B-aligned float4 rows, conflict-free LDS)
#define NSPL  4       // key-range splits per branch
#define BROWS 11      // bias rows addressable by one (chunk, key-quarter) block
#define MSH   16.0f   // fixed exp shift (softmax shift-invariant; fp32-safe here)
#define LOG2E 1.4426950408889634f
#define EPSI  1e-5f

typedef unsigned int u32;

// ---------------- scratch (device globals: no allocation allowed) ----------------
__device__ __align__(16) float g_xq   [BATCH*NN*CC];
__device__ __align__(16) float g_tmax [BATCH*NN*CC];
__device__ __align__(16) float g_tavg [BATCH*NN*CC];
__device__ __align__(16) float g_q    [BATCH*NN*CC];
__device__ __align__(16) float g_kv1  [BATCH*NN*2*CC];
__device__ __align__(16) float g_kv2  [BATCH*NN*2*CC];
__device__ __align__(16) float g_part [2*NSPL][BATCH*NN*CC];   // unnormalized o partials
__device__ __align__(16) float g_l    [2*NSPL][BATCH*NN*NH];   // denominator partials
__device__ __align__(16) float g_small[BATCH*DIM*NN];
__device__ __align__(16) float g_W2   [CC*DIM];
__device__ __align__(16) float g_bb   [DIM];

__device__ __forceinline__ float relu6f(float v) { return fminf(fmaxf(v, 0.f), 6.f); }

__device__ __forceinline__ float tf32r(float x) {
    u32 u; asm("cvt.rna.tf32.f32 %0, %1;" : "=r"(u) : "f"(x));
    return __uint_as_float(u);
}

__device__ __forceinline__ float ex2f(float x) {
    float y; asm("ex2.approx.ftz.f32 %0, %1;" : "=f"(y) : "f"(x));
    return y;
}

// D += A * B  (m16n8k8, tf32 inputs as raw fp32 bits, fp32 accum)
__device__ __forceinline__ void mma8(float4& d, const u32 a0, const u32 a1, const u32 a2, const u32 a3,
                                     u32 b0, u32 b1) {
    asm volatile("mma.sync.aligned.m16n8k8.row.col.f32.tf32.tf32.f32 "
                 "{%0,%1,%2,%3},{%4,%5,%6,%7},{%8,%9},{%0,%1,%2,%3};"
                 : "+f"(d.x), "+f"(d.y), "+f"(d.z), "+f"(d.w)
                 : "r"(a0), "r"(a1), "r"(a2), "r"(a3), "r"(b0), "r"(b1));
}

// ---------------- fold w_proj @ w_out^T and biases ----------------
__global__ void k_prep(const float* __restrict__ wproj, const float* __restrict__ bproj,
                       const float* __restrict__ wout,  const float* __restrict__ bout) {
    int o = blockIdx.x;          // 0..383
    int i = threadIdx.x;         // 0..95
    float acc = 0.f;
    #pragma unroll 8
    for (int c = 0; c < CC; c++) acc += wproj[i*CC + c] * wout[o*CC + c];
    g_W2[i*DIM + o] = acc;
    if (i == 0) {
        float s = 0.f;
        for (int c = 0; c < CC; c++) s += bproj[c] * wout[o*CC + c];
        g_bb[o] = bout[o] + 2.f * s;
    }
}

// ---------------- fused stage1+2 ----------------
__global__ __launch_bounds__(256) void k_stage12(
    const float* __restrict__ x,     const float* __restrict__ w_le,
    const float* __restrict__ b_le,  const float* __restrict__ bn_le,
    const float* __restrict__ w_max, const float* __restrict__ b_max, const float* __restrict__ bn_max,
    const float* __restrict__ w_avg, const float* __restrict__ b_avg, const float* __restrict__ bn_avg)
{
    int n0 = blockIdx.x * 32;
    int c0 = blockIdx.y * 8;
    int b  = blockIdx.z;

    int lane = threadIdx.x & 31;
    int wrp  = threadIdx.x >> 5;
    int c = c0 + wrp;
    int n = n0 + lane;
    int oh = n >> 5, ow = n & 31;

    __shared__ float wS[8*64];
    __shared__ float oS[3][32][9];

    for (int i = threadIdx.x; i < 512; i += 256) wS[i] = w_le[(size_t)c0*64 + i];

    float sle = bn_le [0*CC+c] * rsqrtf(bn_le [3*CC+c] + EPSI);
    float tle = bn_le [1*CC+c] - bn_le [2*CC+c]*sle;
    float smx = bn_max[0*CC+c] * rsqrtf(bn_max[3*CC+c] + EPSI);
    float tmx = bn_max[1*CC+c] - bn_max[2*CC+c]*smx;
    float sav = bn_avg[0*CC+c] * rsqrtf(bn_avg[3*CC+c] + EPSI);
    float tav = bn_avg[1*CC+c] - bn_avg[2*CC+c]*sav;
    float ble = b_le[c], bmx = b_max[c], bav = b_avg[c];
    __syncthreads();

    const float* wc = wS + wrp*64;
    const float* xp = x + (((size_t)(b*DIM + 4*c)*HIN) + 4*oh)*HIN + 4*ow;

    float cv = 0.f, pm = 0.f, pa = 0.f;
    #pragma unroll
    for (int i = 0; i < 4; i++) {
        const float* xpi = xp + (size_t)i*HIN*HIN;
        float mxi = -1e30f, smi = 0.f, cvi = 0.f;
        #pragma unroll
        for (int kh = 0; kh < 4; kh++) {
            float4 v = *(const float4*)(xpi + (size_t)kh*HIN);
            mxi = fmaxf(mxi, fmaxf(fmaxf(v.x, v.y), fmaxf(v.z, v.w)));
            smi += v.x + v.y + v.z + v.w;
            cvi += v.x*wc[i*16+kh*4+0] + v.y*wc[i*16+kh*4+1] + v.z*wc[i*16+kh*4+2] + v.w*wc[i*16+kh*4+3];
        }
        cv += cvi;
        pm += mxi * w_max[c*4+i];
        pa += smi * (1.f/16.f) * w_avg[c*4+i];
    }

    oS[0][lane][wrp] = relu6f((cv + ble)*sle + tle);
    oS[1][lane][wrp] = relu6f((pm + bmx)*smx + tmx);
    oS[2][lane][wrp] = relu6f((pa + bav)*sav + tav);
    __syncthreads();

    int pos = threadIdx.x >> 3, cc = threadIdx.x & 7;
    size_t oidx = (size_t)(b*NN + n0 + pos)*CC + c0 + cc;
    g_xq  [oidx] = oS[0][pos][cc];
    g_tmax[oidx] = oS[1][pos][cc];
    g_tavg[oidx] = oS[2][pos][cc];
}

// ---------------- fused GEMMs on tensor cores: 5 slices of [8192,96]x[96,96] ----------------
__global__ __launch_bounds__(256, 2) void k_gemm_mma(const float* __restrict__ wq,
                                                     const float* __restrict__ wkv,
                                                     float qscale) {
    __shared__ __align__(16) float Ws[CC*WSP];     // 39 KB

    int slice = blockIdx.y;
    const float* in; float* out; const float* W; int Wld, col0, outld; float scale = 1.f;
    switch (slice) {
        case 0:  in = g_xq;   out = g_q;   W = wq;  Wld = CC;   col0 = 0;  outld = CC;   scale = qscale; break;
        case 1:  in = g_tmax; out = g_kv1; W = wkv; Wld = 2*CC; col0 = 0;  outld = 2*CC; break;
        case 2:  in = g_tmax; out = g_kv1; W = wkv; Wld = 2*CC; col0 = CC; outld = 2*CC; break;
        case 3:  in = g_tavg; out = g_kv2; W = wkv; Wld = 2*CC; col0 = 0;  outld = 2*CC; break;
        default: in = g_tavg; out = g_kv2; W = wkv; Wld = 2*CC; col0 = CC; outld = 2*CC; break;
    }

    int tid  = threadIdx.x;
    int warp = tid >> 5, lane = tid & 31;
    int gr = lane >> 2, tg = lane & 3;

    for (int i = tid; i < CC*CC; i += 256) {
        int k = i / CC, j = i % CC;
        Ws[k*WSP + j] = tf32r(W[(size_t)k*Wld + col0 + j]);
    }
    __syncthreads();

    int row = blockIdx.x*128 + warp*16;
    const float* a0p = in + (size_t)(row + gr)*CC;
    const float* a1p = a0p + 8*CC;

    float4 acc[12];
    #pragma unroll
    for (int t = 0; t < 12; t++) acc[t] = make_float4(0.f, 0.f, 0.f, 0.f);

    #pragma unroll
    for (int p = 0; p < 2; p++) {
        u32 A[6][4];
        #pragma unroll
        for (int k8 = 0; k8 < 6; k8++) {
            int kk = p*48 + k8*8;
            A[k8][0] = __float_as_uint(tf32r(a0p[kk + tg]));
            A[k8][1] = __float_as_uint(tf32r(a1p[kk + tg]));
            A[k8][2] = __float_as_uint(tf32r(a0p[kk + tg + 4]));
            A[k8][3] = __float_as_uint(tf32r(a1p[kk + tg + 4]));
        }
        #pragma unroll
        for (int k8 = 0; k8 < 6; k8++) {
            const float* wb = Ws + (p*48 + k8*8 + tg)*WSP + gr;
            #pragma unroll
            for (int n8 = 0; n8 < 12; n8++) {
                u32 b0 = __float_as_uint(wb[n8*8]);
                u32 b1 = __float_as_uint(wb[n8*8 + 4*WSP]);
                mma8(acc[n8], A[k8][0], A[k8][1], A[k8][2], A[k8][3], b0, b1);
            }
        }
    }

    float* o0 = out + (size_t)(row + gr)*outld + col0 + 2*tg;
    float* o1 = o0 + 8*outld;
    #pragma unroll
    for (int n8 = 0; n8 < 12; n8++) {
        *(float2*)(o0 + n8*8) = make_float2(tf32r(acc[n8].x*scale), tf32r(acc[n8].y*scale));
        *(float2*)(o1 + n8*8) = make_float2(tf32r(acc[n8].z*scale), tf32r(acc[n8].w*scale));
    }
}

// ---------------- attention: warp-MMA (tf32), split-K, exp2 w/ folded constants,
// ---------------- k-interleaved QK frags, double-buffered kv ----------------
// q is pre-scaled by log2(e) (folded into qscale); bias smem holds log2e*(bias - MSH),
// so each score is one FADD + one MUFU.EX2. Values identical to exp(s - MSH).
__global__ __launch_bounds__(256, 3) void k_attn(const float* __restrict__ bias_table) {
    int chunk = blockIdx.x;               // 0..7 : 128 queries
    int bh    = blockIdx.y;               // b*NH + h
    int zc    = blockIdx.z;               // 0..7
    int br = zc / NSPL, kq = zc % NSPL;
    int b = bh >> 2, h = bh & 3;
    const float* kv = br ? g_kv2 : g_kv1;
    float* po = g_part[zc];
    float* pl = g_l[zc];

    __shared__ __align__(16) float kT[2][32*KVP];       // 7 KB, double-buffered
    __shared__ __align__(16) float vT[2][32*KVP];       // 7 KB
    __shared__ float biasR[BROWS*63];                   // 2.8 KB

    int tid  = threadIdx.x;
    int warp = tid >> 5, lane = tid & 31;
    int gr = lane >> 2, tg = lane & 3;

    int r0 = chunk*4 + 24 - kq*8;        // lowest bias row (11 rows)
    for (int i = tid; i < BROWS*63; i += 256)
        biasR[i] = (bias_table[(size_t)(r0*63 + i)*NH + h] - MSH) * LOG2E;

    int q0  = chunk*128 + warp*16;
    int yn  = q0 >> 5;
    int xq0 = q0 & 31;

    // Q fragments with interleaved k-slots: slot tg -> physical 2tg, slot tg+4 -> 2tg+1
    u32 qa[3][4];
    {
        const float* qr0 = g_q + (size_t)(b*NN + q0 + gr)*CC + h*HD;
        const float* qr1 = qr0 + 8*CC;
        #pragma unroll
        for (int k8 = 0; k8 < 3; k8++) {
            float2 a0 = *(const float2*)(qr0 + k8*8 + 2*tg);
            float2 a1 = *(const float2*)(qr1 + k8*8 + 2*tg);
            qa[k8][0] = __float_as_uint(a0.x);
            qa[k8][1] = __float_as_uint(a1.x);
            qa[k8][2] = __float_as_uint(a0.y);
            qa[k8][3] = __float_as_uint(a1.y);
        }
    }

    auto prefetch = [&](int bu, int kt) {
        #pragma unroll
        for (int i = tid; i < 384; i += 256) {
            int isv = (i >= 192) ? 1 : 0;
            int jj  = i - isv*192;
            int key = jj / 6, g4 = jj % 6;
            const float* rowp = kv + (size_t)(b*NN + kt*32 + key)*(2*CC) + h*HD + (isv ? CC : 0);
            *(float4*)((isv ? vT[bu] : kT[bu]) + key*KVP + g4*4) = ((const float4*)rowp)[g4];
        }
    };

    float4 ot[3];
    #pragma unroll
    for (int t = 0; t < 3; t++) ot[t] = make_float4(0.f, 0.f, 0.f, 0.f);
    float l0 = 0.f, l1 = 0.f;

    prefetch(0, kq*8);
    __syncthreads();

    for (int i = 0; i < 8; i++) {
        int kt  = kq*8 + i;
        int cur = i & 1;
        if (i + 1 < 8) prefetch(cur ^ 1, kt + 1);

        const float* kC = kT[cur];
        const float* vC = vT[cur];

        // S = Q K^T  (B frag: one float2 per k8 thanks to k-interleave)
        float4 st[4];
        #pragma unroll
        for (int t = 0; t < 4; t++) {
            float4 s = make_float4(0.f, 0.f, 0.f, 0.f);
            const float* kb = kC + (t*8 + gr)*KVP + 2*tg;
            #pragma unroll
            for (int k8 = 0; k8 < 3; k8++) {
                float2 kk = *(const float2*)(kb + k8*8);
                mma8(s, qa[k8][0], qa[k8][1], qa[k8][2], qa[k8][3],
                     __float_as_uint(kk.x), __float_as_uint(kk.y));
            }
            st[t] = s;
        }

        // P = exp2(S' + bias')   (== exp(s - MSH))
        int Cb = (yn - kt + 31 - r0)*63 + xq0 + 31;
        #pragma unroll
        for (int t = 0; t < 4; t++) {
            int col = t*8 + 2*tg;
            st[t].x = ex2f(st[t].x + biasR[Cb + gr - col]);
            st[t].y = ex2f(st[t].y + biasR[Cb + gr - col - 1]);
            st[t].z = ex2f(st[t].z + biasR[Cb + gr + 8 - col]);
            st[t].w = ex2f(st[t].w + biasR[Cb + gr + 8 - col - 1]);
            l0 += st[t].x + st[t].y;
            l1 += st[t].z + st[t].w;
        }

        // O += P V
        #pragma unroll
        for (int g = 0; g < 4; g++) {
            u32 pa0 = __float_as_uint(st[g].x);
            u32 pa1 = __float_as_uint(st[g].z);
            u32 pa2 = __float_as_uint(st[g].y);
            u32 pa3 = __float_as_uint(st[g].w);
            const float* v0 = vC + (g*8 + 2*tg)*KVP;
            const float* v1 = v0 + KVP;
            #pragma unroll
            for (int t = 0; t < 3; t++) {
                u32 b0 = __float_as_uint(v0[t*8 + gr]);
                u32 b1 = __float_as_uint(v1[t*8 + gr]);
                mma8(ot[t], pa0, pa1, pa2, pa3, b0, b1);
            }
        }
        __syncthreads();
    }

    l0 += __shfl_xor_sync(0xFFFFFFFFu, l0, 1);
    l0 += __shfl_xor_sync(0xFFFFFFFFu, l0, 2);
    l1 += __shfl_xor_sync(0xFFFFFFFFu, l1, 1);
    l1 += __shfl_xor_sync(0xFFFFFFFFu, l1, 2);

    size_t qi0 = (size_t)(b*NN + q0 + gr);
    size_t qi1 = qi0 + 8;
    float* or0 = po + qi0*CC + h*HD;
    float* or1 = po + qi1*CC + h*HD;
    #pragma unroll
    for (int t = 0; t < 3; t++) {
        *(float2*)(or0 + t*8 + 2*tg) = make_float2(ot[t].x, ot[t].y);
        *(float2*)(or1 + t*8 + 2*tg) = make_float2(ot[t].z, ot[t].w);
    }
    if (tg == 0) {
        pl[qi0*NH + h] = l0;
        pl[qi1*NH + h] = l1;
    }
}

// ---------------- proj GEMM with fused split-K combine ----------------
__global__ __launch_bounds__(256) void k_proj() {
    __shared__ __align__(16) float inT[CC*ITP];     // padded transpose, 13.5 KB
    __shared__ __align__(16) float Ws [48*128];     // staged half of W2 slice, 24 KB
    __shared__ float invS[2][32][4];                // [branch][row][head] 1/l

    int row0 = blockIdx.x * 32;
    int col0 = blockIdx.y * 128;
    int tid  = threadIdx.x;

    {
        int br = tid >> 7, r = (tid >> 2) & 31, h = tid & 3;
        float ls = 0.f;
        #pragma unroll
        for (int c = 0; c < NSPL; c++) ls += g_l[br*NSPL + c][(size_t)(row0 + r)*NH + h];
        invS[br][r][h] = 1.f / ls;
    }
    __syncthreads();

    for (int i = tid; i < 32*CC; i += 256) {
        int r = i / CC, k = i - r*CC;
        size_t ob = (size_t)(row0 + r)*CC + k;
        float s0 = 0.f, s1 = 0.f;
        #pragma unroll
        for (int c = 0; c < NSPL; c++) { s0 += g_part[c][ob]; s1 += g_part[NSPL + c][ob]; }
        int h = k / HD;
        inT[k*ITP + r] = s0*invS[0][r][h] + s1*invS[1][r][h];
    }

    int rb = tid & 7;
    int cb = tid >> 3;

    float4 acc0 = {0,0,0,0}, acc1 = {0,0,0,0}, acc2 = {0,0,0,0}, acc3 = {0,0,0,0};
    for (int p = 0; p < 2; p++) {
        __syncthreads();
        for (int i = tid; i < 48*128; i += 256) {
            int k = i >> 7, j = i & 127;
            Ws[i] = g_W2[(size_t)(p*48 + k)*DIM + col0 + j];
        }
        __syncthreads();
        #pragma unroll 4
        for (int k = 0; k < 48; k++) {
            float4 w = *(const float4*)(Ws + k*128 + cb*4);
            float4 a = *(const float4*)(inT + (p*48 + k)*ITP + rb*4);
            acc0.x += a.x*w.x; acc0.y += a.x*w.y; acc0.z += a.x*w.z; acc0.w += a.x*w.w;
            acc1.x += a.y*w.x; acc1.y += a.y*w.y; acc1.z += a.y*w.z; acc1.w += a.y*w.w;
            acc2.x += a.z*w.x; acc2.y += a.z*w.y; acc2.z += a.z*w.z; acc2.w += a.z*w.w;
            acc3.x += a.w*w.x; acc3.y += a.w*w.y; acc3.z += a.w*w.z; acc3.w += a.w*w.w;
        }
    }

    int b  = row0 >> 10;
    int n0 = (row0 & 1023) + rb*4;
    float bb0 = g_bb[col0 + cb*4], bb1 = g_bb[col0 + cb*4 + 1];
    float bb2 = g_bb[col0 + cb*4 + 2], bb3 = g_bb[col0 + cb*4 + 3];
    float4 s0 = make_float4(acc0.x + bb0, acc1.x + bb0, acc2.x + bb0, acc3.x + bb0);
    float4 s1 = make_float4(acc0.y + bb1, acc1.y + bb1, acc2.y + bb1, acc3.y + bb1);
    float4 s2 = make_float4(acc0.z + bb2, acc1.z + bb2, acc2.z + bb2, acc3.z + bb2);
    float4 s3 = make_float4(acc0.w + bb3, acc1.w + bb3, acc2.w + bb3, acc3.w + bb3);
    *(float4*)(g_small + ((size_t)(b*DIM) + col0 + cb*4    )*NN + n0) = s0;
    *(float4*)(g_small + ((size_t)(b*DIM) + col0 + cb*4 + 1)*NN + n0) = s1;
    *(float4*)(g_small + ((size_t)(b*DIM) + col0 + cb*4 + 2)*NN + n0) = s2;
    *(float4*)(g_small + ((size_t)(b*DIM) + col0 + cb*4 + 3)*NN + n0) = s3;
}

// ---------------- bilinear x4 upsample, align_corners=True (float4 stores) ----------------
__global__ __launch_bounds__(256) void k_upsample(float* __restrict__ out) {
    int plane = blockIdx.x;  // b*DIM + channel
    __shared__ float pl[NN];
    for (int i = threadIdx.x; i < NN; i += 256) pl[i] = g_small[(size_t)plane*NN + i];
    __syncthreads();

    const float sc = 31.f / 127.f;
    float* op = out + (size_t)plane*128*128;
    for (int idx = threadIdx.x; idx < 4096; idx += 256) {
        int yo = idx >> 5, xq = (idx & 31) * 4;
        float fy = yo * sc; int y0 = (int)fy; float wy = fy - y0; int y1 = min(y0+1, 31);
        const float* r0 = pl + y0*32;
        const float* r1 = pl + y1*32;
        float4 o;
        float* po = &o.x;
        #pragma unroll
        for (int u = 0; u < 4; u++) {
            int xo = xq + u;
            float fx = xo * sc; int x0 = (int)fx; float wx = fx - x0; int x1 = min(x0+1, 31);
            float top = r0[x0] + (r0[x1] - r0[x0])*wx;
            float bot = r1[x0] + (r1[x1] - r1[x0])*wx;
            po[u] = top + (bot - top)*wy;
        }
        *(float4*)(op + yo*128 + xq) = o;
    }
}

// ---------------- launch ----------------
extern "C" void kernel_launch(void* const* d_in, const int* in_sizes, int n_in,
                              void* d_out, int out_size) {
    const float* x        = (const float*)d_in[0];
    const float* w_le     = (const float*)d_in[1];
    const float* b_le     = (const float*)d_in[2];
    const float* bn_le    = (const float*)d_in[3];
    const float* w_max    = (const float*)d_in[4];
    const float* b_max    = (const float*)d_in[5];
    const float* bn_max   = (const float*)d_in[6];
    const float* w_avg    = (const float*)d_in[7];
    const float* b_avg    = (const float*)d_in[8];
    const float* bn_avg   = (const float*)d_in[9];
    const float* bias_tab = (const float*)d_in[10];
    const float* w_q      = (const float*)d_in[11];
    const float* w_kv     = (const float*)d_in[12];
    const float* w_proj   = (const float*)d_in[13];
    const float* b_proj   = (const float*)d_in[14];
    const float* w_out    = (const float*)d_in[15];
    const float* b_out    = (const float*)d_in[16];
    float* out = (float*)d_out;

    // 1/sqrt(24) * log2(e): folds the exp->exp2 conversion into q
    const float qscale = (float)(0.20412414523193154 * 1.4426950408889634);

    k_prep    <<<DIM, CC>>>(w_proj, b_proj, w_out, b_out);
    k_stage12 <<<dim3(32, 12, BATCH), 256>>>(x, w_le, b_le, bn_le,
                                             w_max, b_max, bn_max, w_avg, b_avg, bn_avg);

    k_gemm_mma<<<dim3(64, 5), 256>>>(w_q, w_kv, qscale);

    k_attn    <<<dim3(8, NH*BATCH, 2*NSPL), 256>>>(bias_tab);
    k_proj    <<<dim3(256, 3), 256>>>();
    k_upsample<<<BATCH*DIM, 256>>>(out);
}

// round 16
// speedup vs baseline: 1.0652x; 1.0652x over previous
#include <cuda_runtime.h>

#define BATCH 8
#define DIM   384
#define CC    96
#define HIN   128
#define NN    1024
#define NH    4
#define HD    24
#define KVP   28      // padded kv smem row (conflict-free mma B loads)
#define WSP   104     // padded W smem row stride (conflict-free B frags)
#define ITP   36      // padded inT row stride (16B-aligned float4 rows, conflict-free LDS)
#define NSPL  4       // key-range splits per branch
#define BROWS 15      // bias rows addressable by one (chunk, key-quarter) block
#define MSH   16.0f   // fixed exp shift (softmax shift-invariant; fp32-safe here)
#define LOG2E 1.4426950408889634f
#define EPSI  1e-5f

typedef unsigned int u32;

// ---------------- scratch (device globals: no allocation allowed) ----------------
__device__ __align__(16) float g_xq   [BATCH*NN*CC];
__device__ __align__(16) float g_tmax [BATCH*NN*CC];
__device__ __align__(16) float g_tavg [BATCH*NN*CC];
__device__ __align__(16) float g_q    [BATCH*NN*CC];
__device__ __align__(16) float g_kv1  [BATCH*NN*2*CC];
__device__ __align__(16) float g_kv2  [BATCH*NN*2*CC];
__device__ __align__(16) float g_part [2*NSPL][BATCH*NN*CC];   // unnormalized o partials
__device__ __align__(16) float g_l    [2*NSPL][BATCH*NN*NH];   // denominator partials
__device__ __align__(16) float g_small[BATCH*DIM*NN];
__device__ __align__(16) float g_W2   [CC*DIM];
__device__ __align__(16) float g_bb   [DIM];

__device__ __forceinline__ float relu6f(float v) { return fminf(fmaxf(v, 0.f), 6.f); }

__device__ __forceinline__ float tf32r(float x) {
    u32 u; asm("cvt.rna.tf32.f32 %0, %1;" : "=r"(u) : "f"(x));
    return __uint_as_float(u);
}

__device__ __forceinline__ float ex2f(float x) {
    float y; asm("ex2.approx.ftz.f32 %0, %1;" : "=f"(y) : "f"(x));
    return y;
}

// D += A * B  (m16n8k8, tf32 inputs as raw fp32 bits, fp32 accum)
__device__ __forceinline__ void mma8(float4& d, const u32 a0, const u32 a1, const u32 a2, const u32 a3,
                                     u32 b0, u32 b1) {
    asm volatile("mma.sync.aligned.m16n8k8.row.col.f32.tf32.tf32.f32 "
                 "{%0,%1,%2,%3},{%4,%5,%6,%7},{%8,%9},{%0,%1,%2,%3};"
                 : "+f"(d.x), "+f"(d.y), "+f"(d.z), "+f"(d.w)
                 : "r"(a0), "r"(a1), "r"(a2), "r"(a3), "r"(b0), "r"(b1));
}

// ---------------- fold w_proj @ w_out^T and biases ----------------
__global__ void k_prep(const float* __restrict__ wproj, const float* __restrict__ bproj,
                       const float* __restrict__ wout,  const float* __restrict__ bout) {
    int o = blockIdx.x;          // 0..383
    int i = threadIdx.x;         // 0..95
    float acc = 0.f;
    #pragma unroll 8
    for (int c = 0; c < CC; c++) acc += wproj[i*CC + c] * wout[o*CC + c];
    g_W2[i*DIM + o] = acc;
    if (i == 0) {
        float s = 0.f;
        for (int c = 0; c < CC; c++) s += bproj[c] * wout[o*CC + c];
        g_bb[o] = bout[o] + 2.f * s;
    }
}

// ---------------- fused stage1+2 ----------------
__global__ __launch_bounds__(256) void k_stage12(
    const float* __restrict__ x,     const float* __restrict__ w_le,
    const float* __restrict__ b_le,  const float* __restrict__ bn_le,
    const float* __restrict__ w_max, const float* __restrict__ b_max, const float* __restrict__ bn_max,
    const float* __restrict__ w_avg, const float* __restrict__ b_avg, const float* __restrict__ bn_avg)
{
    int n0 = blockIdx.x * 32;
    int c0 = blockIdx.y * 8;
    int b  = blockIdx.z;

    int lane = threadIdx.x & 31;
    int wrp  = threadIdx.x >> 5;
    int c = c0 + wrp;
    int n = n0 + lane;
    int oh = n >> 5, ow = n & 31;

    __shared__ float wS[8*64];
    __shared__ float oS[3][32][9];

    for (int i = threadIdx.x; i < 512; i += 256) wS[i] = w_le[(size_t)c0*64 + i];

    float sle = bn_le [0*CC+c] * rsqrtf(bn_le [3*CC+c] + EPSI);
    float tle = bn_le [1*CC+c] - bn_le [2*CC+c]*sle;
    float smx = bn_max[0*CC+c] * rsqrtf(bn_max[3*CC+c] + EPSI);
    float tmx = bn_max[1*CC+c] - bn_max[2*CC+c]*smx;
    float sav = bn_avg[0*CC+c] * rsqrtf(bn_avg[3*CC+c] + EPSI);
    float tav = bn_avg[1*CC+c] - bn_avg[2*CC+c]*sav;
    float ble = b_le[c], bmx = b_max[c], bav = b_avg[c];
    __syncthreads();

    const float* wc = wS + wrp*64;
    const float* xp = x + (((size_t)(b*DIM + 4*c)*HIN) + 4*oh)*HIN + 4*ow;

    float cv = 0.f, pm = 0.f, pa = 0.f;
    #pragma unroll
    for (int i = 0; i < 4; i++) {
        const float* xpi = xp + (size_t)i*HIN*HIN;
        float mxi = -1e30f, smi = 0.f, cvi = 0.f;
        #pragma unroll
        for (int kh = 0; kh < 4; kh++) {
            float4 v = *(const float4*)(xpi + (size_t)kh*HIN);
            mxi = fmaxf(mxi, fmaxf(fmaxf(v.x, v.y), fmaxf(v.z, v.w)));
            smi += v.x + v.y + v.z + v.w;
            cvi += v.x*wc[i*16+kh*4+0] + v.y*wc[i*16+kh*4+1] + v.z*wc[i*16+kh*4+2] + v.w*wc[i*16+kh*4+3];
        }
        cv += cvi;
        pm += mxi * w_max[c*4+i];
        pa += smi * (1.f/16.f) * w_avg[c*4+i];
    }

    oS[0][lane][wrp] = relu6f((cv + ble)*sle + tle);
    oS[1][lane][wrp] = relu6f((pm + bmx)*smx + tmx);
    oS[2][lane][wrp] = relu6f((pa + bav)*sav + tav);
    __syncthreads();

    int pos = threadIdx.x >> 3, cc = threadIdx.x & 7;
    size_t oidx = (size_t)(b*NN + n0 + pos)*CC + c0 + cc;
    g_xq  [oidx] = oS[0][pos][cc];
    g_tmax[oidx] = oS[1][pos][cc];
    g_tavg[oidx] = oS[2][pos][cc];
}

// ---------------- fused GEMMs on tensor cores: 5 slices of [8192,96]x[96,96] ----------------
__global__ __launch_bounds__(256, 2) void k_gemm_mma(const float* __restrict__ wq,
                                                     const float* __restrict__ wkv,
                                                     float qscale) {
    __shared__ __align__(16) float Ws[CC*WSP];     // 39 KB

    int slice = blockIdx.y;
    const float* in; float* out; const float* W; int Wld, col0, outld; float scale = 1.f;
    switch (slice) {
        case 0:  in = g_xq;   out = g_q;   W = wq;  Wld = CC;   col0 = 0;  outld = CC;   scale = qscale; break;
        case 1:  in = g_tmax; out = g_kv1; W = wkv; Wld = 2*CC; col0 = 0;  outld = 2*CC; break;
        case 2:  in = g_tmax; out = g_kv1; W = wkv; Wld = 2*CC; col0 = CC; outld = 2*CC; break;
        case 3:  in = g_tavg; out = g_kv2; W = wkv; Wld = 2*CC; col0 = 0;  outld = 2*CC; break;
        default: in = g_tavg; out = g_kv2; W = wkv; Wld = 2*CC; col0 = CC; outld = 2*CC; break;
    }

    int tid  = threadIdx.x;
    int warp = tid >> 5, lane = tid & 31;
    int gr = lane >> 2, tg = lane & 3;

    for (int i = tid; i < CC*CC; i += 256) {
        int k = i / CC, j = i % CC;
        Ws[k*WSP + j] = tf32r(W[(size_t)k*Wld + col0 + j]);
    }
    __syncthreads();

    int row = blockIdx.x*128 + warp*16;
    const float* a0p = in + (size_t)(row + gr)*CC;
    const float* a1p = a0p + 8*CC;

    float4 acc[12];
    #pragma unroll
    for (int t = 0; t < 12; t++) acc[t] = make_float4(0.f, 0.f, 0.f, 0.f);

    #pragma unroll
    for (int p = 0; p < 2; p++) {
        u32 A[6][4];
        #pragma unroll
        for (int k8 = 0; k8 < 6; k8++) {
            int kk = p*48 + k8*8;
            A[k8][0] = __float_as_uint(tf32r(a0p[kk + tg]));
            A[k8][1] = __float_as_uint(tf32r(a1p[kk + tg]));
            A[k8][2] = __float_as_uint(tf32r(a0p[kk + tg + 4]));
            A[k8][3] = __float_as_uint(tf32r(a1p[kk + tg + 4]));
        }
        #pragma unroll
        for (int k8 = 0; k8 < 6; k8++) {
            const float* wb = Ws + (p*48 + k8*8 + tg)*WSP + gr;
            #pragma unroll
            for (int n8 = 0; n8 < 12; n8++) {
                u32 b0 = __float_as_uint(wb[n8*8]);
                u32 b1 = __float_as_uint(wb[n8*8 + 4*WSP]);
                mma8(acc[n8], A[k8][0], A[k8][1], A[k8][2], A[k8][3], b0, b1);
            }
        }
    }

    float* o0 = out + (size_t)(row + gr)*outld + col0 + 2*tg;
    float* o1 = o0 + 8*outld;
    #pragma unroll
    for (int n8 = 0; n8 < 12; n8++) {
        *(float2*)(o0 + n8*8) = make_float2(tf32r(acc[n8].x*scale), tf32r(acc[n8].y*scale));
        *(float2*)(o1 + n8*8) = make_float2(tf32r(acc[n8].z*scale), tf32r(acc[n8].w*scale));
    }
}

// ---------------- attention: warp-MMA (tf32), split-K, exp2 w/ folded constants,
// ---------------- TWO m16 tiles per warp (B-frags amortized), double-buffered kv ----------------
__global__ __launch_bounds__(256, 2) void k_attn(const float* __restrict__ bias_table) {
    int chunk = blockIdx.x;               // 0..3 : 256 queries
    int bh    = blockIdx.y;               // b*NH + h
    int zc    = blockIdx.z;               // 0..7
    int br = zc / NSPL, kq = zc % NSPL;
    int b = bh >> 2, h = bh & 3;
    const float* kv = br ? g_kv2 : g_kv1;
    float* po = g_part[zc];
    float* pl = g_l[zc];

    __shared__ __align__(16) float kT[2][32*KVP];       // 7 KB, double-buffered
    __shared__ __align__(16) float vT[2][32*KVP];       // 7 KB
    __shared__ float biasR[BROWS*63];                   // 3.7 KB

    int tid  = threadIdx.x;
    int warp = tid >> 5, lane = tid & 31;
    int gr = lane >> 2, tg = lane & 3;

    // bias rows: yn in [chunk*8, chunk*8+7], kt in [kq*8, kq*8+7] -> 15 rows
    int r0 = chunk*8 + 24 - kq*8;
    for (int i = tid; i < BROWS*63; i += 256)
        biasR[i] = (bias_table[(size_t)(r0*63 + i)*NH + h] - MSH) * LOG2E;

    int q0 = chunk*256 + warp*32;         // warp owns one full image row: tiles q0, q0+16
    int yn = q0 >> 5;

    // Q fragments for both tiles, interleaved k-slots (slot tg -> 2tg, tg+4 -> 2tg+1)
    u32 qa[2][3][4];
    #pragma unroll
    for (int mt = 0; mt < 2; mt++) {
        const float* qr0 = g_q + (size_t)(b*NN + q0 + mt*16 + gr)*CC + h*HD;
        const float* qr1 = qr0 + 8*CC;
        #pragma unroll
        for (int k8 = 0; k8 < 3; k8++) {
            float2 a0 = *(const float2*)(qr0 + k8*8 + 2*tg);
            float2 a1 = *(const float2*)(qr1 + k8*8 + 2*tg);
            qa[mt][k8][0] = __float_as_uint(a0.x);
            qa[mt][k8][1] = __float_as_uint(a1.x);
            qa[mt][k8][2] = __float_as_uint(a0.y);
            qa[mt][k8][3] = __float_as_uint(a1.y);
        }
    }

    auto prefetch = [&](int bu, int kt) {
        #pragma unroll
        for (int i = tid; i < 384; i += 256) {
            int isv = (i >= 192) ? 1 : 0;
            int jj  = i - isv*192;
            int key = jj / 6, g4 = jj % 6;
            const float* rowp = kv + (size_t)(b*NN + kt*32 + key)*(2*CC) + h*HD + (isv ? CC : 0);
            *(float4*)((isv ? vT[bu] : kT[bu]) + key*KVP + g4*4) = ((const float4*)rowp)[g4];
        }
    };

    float4 otA[3], otB[3];
    #pragma unroll
    for (int t = 0; t < 3; t++) { otA[t] = make_float4(0.f,0.f,0.f,0.f); otB[t] = make_float4(0.f,0.f,0.f,0.f); }
    float lA0 = 0.f, lA1 = 0.f, lB0 = 0.f, lB1 = 0.f;

    prefetch(0, kq*8);
    __syncthreads();

    for (int i = 0; i < 8; i++) {
        int kt  = kq*8 + i;
        int cur = i & 1;
        if (i + 1 < 8) prefetch(cur ^ 1, kt + 1);

        const float* kC = kT[cur];
        const float* vC = vT[cur];

        // S = Q K^T for both tiles, sharing each B fragment
        float4 sA[4], sB[4];
        #pragma unroll
        for (int t = 0; t < 4; t++) {
            float4 a = make_float4(0.f,0.f,0.f,0.f), bvv = make_float4(0.f,0.f,0.f,0.f);
            const float* kb = kC + (t*8 + gr)*KVP + 2*tg;
            #pragma unroll
            for (int k8 = 0; k8 < 3; k8++) {
                float2 kk = *(const float2*)(kb + k8*8);
                u32 b0 = __float_as_uint(kk.x), b1 = __float_as_uint(kk.y);
                mma8(a,   qa[0][k8][0], qa[0][k8][1], qa[0][k8][2], qa[0][k8][3], b0, b1);
                mma8(bvv, qa[1][k8][0], qa[1][k8][1], qa[1][k8][2], qa[1][k8][3], b0, b1);
            }
            sA[t] = a; sB[t] = bvv;
        }

        // P = exp2(S' + bias')
        int Cb = (yn - kt + 31 - r0)*63 + 31;       // xq0 = 0 for tile A; +16 for tile B
        #pragma unroll
        for (int t = 0; t < 4; t++) {
            int col = t*8 + 2*tg;
            sA[t].x = ex2f(sA[t].x + biasR[Cb + gr - col]);
            sA[t].y = ex2f(sA[t].y + biasR[Cb + gr - col - 1]);
            sA[t].z = ex2f(sA[t].z + biasR[Cb + gr + 8 - col]);
            sA[t].w = ex2f(sA[t].w + biasR[Cb + gr + 8 - col - 1]);
            lA0 += sA[t].x + sA[t].y;
            lA1 += sA[t].z + sA[t].w;
            sB[t].x = ex2f(sB[t].x + biasR[Cb + 16 + gr - col]);
            sB[t].y = ex2f(sB[t].y + biasR[Cb + 16 + gr - col - 1]);
            sB[t].z = ex2f(sB[t].z + biasR[Cb + 16 + gr + 8 - col]);
            sB[t].w = ex2f(sB[t].w + biasR[Cb + 16 + gr + 8 - col - 1]);
            lB0 += sB[t].x + sB[t].y;
            lB1 += sB[t].z + sB[t].w;
        }

        // O += P V for both tiles, sharing each B fragment
        #pragma unroll
        for (int g = 0; g < 4; g++) {
            u32 pA0 = __float_as_uint(sA[g].x), pA1 = __float_as_uint(sA[g].z);
            u32 pA2 = __float_as_uint(sA[g].y), pA3 = __float_as_uint(sA[g].w);
            u32 pB0 = __float_as_uint(sB[g].x), pB1 = __float_as_uint(sB[g].z);
            u32 pB2 = __float_as_uint(sB[g].y), pB3 = __float_as_uint(sB[g].w);
            const float* v0 = vC + (g*8 + 2*tg)*KVP;
            const float* v1 = v0 + KVP;
            #pragma unroll
            for (int t = 0; t < 3; t++) {
                u32 b0 = __float_as_uint(v0[t*8 + gr]);
                u32 b1 = __float_as_uint(v1[t*8 + gr]);
                mma8(otA[t], pA0, pA1, pA2, pA3, b0, b1);
                mma8(otB[t], pB0, pB1, pB2, pB3, b0, b1);
            }
        }
        __syncthreads();
    }

    lA0 += __shfl_xor_sync(0xFFFFFFFFu, lA0, 1); lA0 += __shfl_xor_sync(0xFFFFFFFFu, lA0, 2);
    lA1 += __shfl_xor_sync(0xFFFFFFFFu, lA1, 1); lA1 += __shfl_xor_sync(0xFFFFFFFFu, lA1, 2);
    lB0 += __shfl_xor_sync(0xFFFFFFFFu, lB0, 1); lB0 += __shfl_xor_sync(0xFFFFFFFFu, lB0, 2);
    lB1 += __shfl_xor_sync(0xFFFFFFFFu, lB1, 1); lB1 += __shfl_xor_sync(0xFFFFFFFFu, lB1, 2);

    size_t qiA0 = (size_t)(b*NN + q0 + gr),      qiA1 = qiA0 + 8;
    size_t qiB0 = qiA0 + 16,                      qiB1 = qiA0 + 24;
    float* oA0 = po + qiA0*CC + h*HD;  float* oA1 = po + qiA1*CC + h*HD;
    float* oB0 = po + qiB0*CC + h*HD;  float* oB1 = po + qiB1*CC + h*HD;
    #pragma unroll
    for (int t = 0; t < 3; t++) {
        *(float2*)(oA0 + t*8 + 2*tg) = make_float2(otA[t].x, otA[t].y);
        *(float2*)(oA1 + t*8 + 2*tg) = make_float2(otA[t].z, otA[t].w);
        *(float2*)(oB0 + t*8 + 2*tg) = make_float2(otB[t].x, otB[t].y);
        *(float2*)(oB1 + t*8 + 2*tg) = make_float2(otB[t].z, otB[t].w);
    }
    if (tg == 0) {
        pl[qiA0*NH + h] = lA0;
        pl[qiA1*NH + h] = lA1;
        pl[qiB0*NH + h] = lB0;
        pl[qiB1*NH + h] = lB1;
    }
}

// ---------------- proj GEMM with fused split-K combine ----------------
__global__ __launch_bounds__(256) void k_proj() {
    __shared__ __align__(16) float inT[CC*ITP];     // padded transpose, 13.5 KB
    __shared__ __align__(16) float Ws [48*128];     // staged half of W2 slice, 24 KB
    __shared__ float invS[2][32][4];                // [branch][row][head] 1/l

    int row0 = blockIdx.x * 32;
    int col0 = blockIdx.y * 128;
    int tid  = threadIdx.x;

    {
        int br = tid >> 7, r = (tid >> 2) & 31, h = tid & 3;
        float ls = 0.f;
        #pragma unroll
        for (int c = 0; c < NSPL; c++) ls += g_l[br*NSPL + c][(size_t)(row0 + r)*NH + h];
        invS[br][r][h] = 1.f / ls;
    }
    __syncthreads();

    for (int i = tid; i < 32*CC; i += 256) {
        int r = i / CC, k = i - r*CC;
        size_t ob = (size_t)(row0 + r)*CC + k;
        float s0 = 0.f, s1 = 0.f;
        #pragma unroll
        for (int c = 0; c < NSPL; c++) { s0 += g_part[c][ob]; s1 += g_part[NSPL + c][ob]; }
        int h = k / HD;
        inT[k*ITP + r] = s0*invS[0][r][h] + s1*invS[1][r][h];
    }

    int rb = tid & 7;
    int cb = tid >> 3;

    float4 acc0 = {0,0,0,0}, acc1 = {0,0,0,0}, acc2 = {0,0,0,0}, acc3 = {0,0,0,0};
    for (int p = 0; p < 2; p++) {
        __syncthreads();
        for (int i = tid; i < 48*128; i += 256) {
            int k = i >> 7, j = i & 127;
            Ws[i] = g_W2[(size_t)(p*48 + k)*DIM + col0 + j];
        }
        __syncthreads();
        #pragma unroll 4
        for (int k = 0; k < 48; k++) {
            float4 w = *(const float4*)(Ws + k*128 + cb*4);
            float4 a = *(const float4*)(inT + (p*48 + k)*ITP + rb*4);
            acc0.x += a.x*w.x; acc0.y += a.x*w.y; acc0.z += a.x*w.z; acc0.w += a.x*w.w;
            acc1.x += a.y*w.x; acc1.y += a.y*w.y; acc1.z += a.y*w.z; acc1.w += a.y*w.w;
            acc2.x += a.z*w.x; acc2.y += a.z*w.y; acc2.z += a.z*w.z; acc2.w += a.z*w.w;
            acc3.x += a.w*w.x; acc3.y += a.w*w.y; acc3.z += a.w*w.z; acc3.w += a.w*w.w;
        }
    }

    int b  = row0 >> 10;
    int n0 = (row0 & 1023) + rb*4;
    float bb0 = g_bb[col0 + cb*4], bb1 = g_bb[col0 + cb*4 + 1];
    float bb2 = g_bb[col0 + cb*4 + 2], bb3 = g_bb[col0 + cb*4 + 3];
    float4 s0 = make_float4(acc0.x + bb0, acc1.x + bb0, acc2.x + bb0, acc3.x + bb0);
    float4 s1 = make_float4(acc0.y + bb1, acc1.y + bb1, acc2.y + bb1, acc3.y + bb1);
    float4 s2 = make_float4(acc0.z + bb2, acc1.z + bb2, acc2.z + bb2, acc3.z + bb2);
    float4 s3 = make_float4(acc0.w + bb3, acc1.w + bb3, acc2.w + bb3, acc3.w + bb3);
    *(float4*)(g_small + ((size_t)(b*DIM) + col0 + cb*4    )*NN + n0) = s0;
    *(float4*)(g_small + ((size_t)(b*DIM) + col0 + cb*4 + 1)*NN + n0) = s1;
    *(float4*)(g_small + ((size_t)(b*DIM) + col0 + cb*4 + 2)*NN + n0) = s2;
    *(float4*)(g_small + ((size_t)(b*DIM) + col0 + cb*4 + 3)*NN + n0) = s3;
}

// ---------------- bilinear x4 upsample, align_corners=True (float4 stores) ----------------
__global__ __launch_bounds__(256) void k_upsample(float* __restrict__ out) {
    int plane = blockIdx.x;  // b*DIM + channel
    __shared__ float pl[NN];
    for (int i = threadIdx.x; i < NN; i += 256) pl[i] = g_small[(size_t)plane*NN + i];
    __syncthreads();

    const float sc = 31.f / 127.f;
    float* op = out + (size_t)plane*128*128;
    for (int idx = threadIdx.x; idx < 4096; idx += 256) {
        int yo = idx >> 5, xq = (idx & 31) * 4;
        float fy = yo * sc; int y0 = (int)fy; float wy = fy - y0; int y1 = min(y0+1, 31);
        const float* r0 = pl + y0*32;
        const float* r1 = pl + y1*32;
        float4 o;
        float* po = &o.x;
        #pragma unroll
        for (int u = 0; u < 4; u++) {
            int xo = xq + u;
            float fx = xo * sc; int x0 = (int)fx; float wx = fx - x0; int x1 = min(x0+1, 31);
            float top = r0[x0] + (r0[x1] - r0[x0])*wx;
            float bot = r1[x0] + (r1[x1] - r1[x0])*wx;
            po[u] = top + (bot - top)*wy;
        }
        *(float4*)(op + yo*128 + xq) = o;
    }
}

// ---------------- launch ----------------
extern "C" void kernel_launch(void* const* d_in, const int* in_sizes, int n_in,
                              void* d_out, int out_size) {
    const float* x        = (const float*)d_in[0];
    const float* w_le     = (const float*)d_in[1];
    const float* b_le     = (const float*)d_in[2];
    const float* bn_le    = (const float*)d_in[3];
    const float* w_max    = (const float*)d_in[4];
    const float* b_max    = (const float*)d_in[5];
    const float* bn_max   = (const float*)d_in[6];
    const float* w_avg    = (const float*)d_in[7];
    const float* b_avg    = (const float*)d_in[8];
    const float* bn_avg   = (const float*)d_in[9];
    const float* bias_tab = (const float*)d_in[10];
    const float* w_q      = (const float*)d_in[11];
    const float* w_kv     = (const float*)d_in[12];
    const float* w_proj   = (const float*)d_in[13];
    const float* b_proj   = (const float*)d_in[14];
    const float* w_out    = (const float*)d_in[15];
    const float* b_out    = (const float*)d_in[16];
    float* out = (float*)d_out;

    // 1/sqrt(24) * log2(e): folds the exp->exp2 conversion into q
    const float qscale = (float)(0.20412414523193154 * 1.4426950408889634);

    k_prep    <<<DIM, CC>>>(w_proj, b_proj, w_out, b_out);
    k_stage12 <<<dim3(32, 12, BATCH), 256>>>(x, w_le, b_le, bn_le,
                                             w_max, b_max, bn_max, w_avg, b_avg, bn_avg);

    k_gemm_mma<<<dim3(64, 5), 256>>>(w_q, w_kv, qscale);

    k_attn    <<<dim3(4, NH*BATCH, 2*NSPL), 256>>>(bias_tab);
    k_proj    <<<dim3(256, 3), 256>>>();
    k_upsample<<<BATCH*DIM, 256>>>(out);
}